// round 1
// baseline (speedup 1.0000x reference)
#include <cuda_runtime.h>

// GraphAttentionPooling: B=196608 rows of F=256 fp32, pooled in groups of P=3
// via softmax(x_p . w) attention. Output [G=65536, 256] fp32.
//
// One warp per group. Each lane owns 8 floats (2x float4) of each of the 3
// rows: one coalesced read sweep, scores via shfl reduction, softmax in
// registers (bias cancels), weighted sum from registers, coalesced store.

constexpr int F = 256;           // in_features
constexpr int P = 3;             // pooling size
constexpr int WARPS_PER_BLOCK = 8;
constexpr int THREADS = WARPS_PER_BLOCK * 32;

__global__ __launch_bounds__(THREADS)
void gap_kernel(const float* __restrict__ x,
                const float* __restrict__ w,
                float* __restrict__ out,
                int num_groups) {
    __shared__ float ws[F];
    int tid = threadIdx.x;
    ws[tid] = w[tid];
    __syncthreads();

    int warp = tid >> 5;
    int lane = tid & 31;
    int g = blockIdx.x * WARPS_PER_BLOCK + warp;
    if (g >= num_groups) return;

    // Each lane: 8 contiguous floats = 2 float4, at float offset lane*8.
    const float4* wsv = reinterpret_cast<const float4*>(ws) + lane * 2;
    float4 w0 = wsv[0];
    float4 w1 = wsv[1];

    const float4* xg = reinterpret_cast<const float4*>(x) + (size_t)g * (P * F / 4);

    float4 r[P][2];
    float s[P];

    #pragma unroll
    for (int p = 0; p < P; p++) {
        const float4* row = xg + p * (F / 4);
        r[p][0] = row[lane * 2];
        r[p][1] = row[lane * 2 + 1];
        float d = r[p][0].x * w0.x + r[p][0].y * w0.y
                + r[p][0].z * w0.z + r[p][0].w * w0.w
                + r[p][1].x * w1.x + r[p][1].y * w1.y
                + r[p][1].z * w1.z + r[p][1].w * w1.w;
        #pragma unroll
        for (int off = 16; off > 0; off >>= 1)
            d += __shfl_xor_sync(0xFFFFFFFFu, d, off);
        s[p] = d;
    }

    // Softmax over P=3 scalars (bias adds the same constant to every score,
    // so it cancels — skip it). All lanes compute identically.
    float m = fmaxf(s[0], fmaxf(s[1], s[2]));
    float e0 = __expf(s[0] - m);
    float e1 = __expf(s[1] - m);
    float e2 = __expf(s[2] - m);
    float inv = 1.0f / (e0 + e1 + e2);
    float a0 = e0 * inv, a1 = e1 * inv, a2 = e2 * inv;

    float4 o0, o1;
    o0.x = a0 * r[0][0].x + a1 * r[1][0].x + a2 * r[2][0].x;
    o0.y = a0 * r[0][0].y + a1 * r[1][0].y + a2 * r[2][0].y;
    o0.z = a0 * r[0][0].z + a1 * r[1][0].z + a2 * r[2][0].z;
    o0.w = a0 * r[0][0].w + a1 * r[1][0].w + a2 * r[2][0].w;
    o1.x = a0 * r[0][1].x + a1 * r[1][1].x + a2 * r[2][1].x;
    o1.y = a0 * r[0][1].y + a1 * r[1][1].y + a2 * r[2][1].y;
    o1.z = a0 * r[0][1].z + a1 * r[1][1].z + a2 * r[2][1].z;
    o1.w = a0 * r[0][1].w + a1 * r[1][1].w + a2 * r[2][1].w;

    float4* og = reinterpret_cast<float4*>(out) + (size_t)g * (F / 4);
    og[lane * 2] = o0;
    og[lane * 2 + 1] = o1;
}

extern "C" void kernel_launch(void* const* d_in, const int* in_sizes, int n_in,
                              void* d_out, int out_size) {
    const float* batch_rep = (const float*)d_in[0];   // [B, 256] fp32
    const float* W_weight  = (const float*)d_in[1];   // [1, 256] fp32
    // d_in[2] = W_bias [1] — cancels in softmax, unused.
    float* out = (float*)d_out;                       // [G, 256] fp32

    int batch = in_sizes[0] / F;       // 196608
    int num_groups = batch / P;        // 65536

    int blocks = (num_groups + WARPS_PER_BLOCK - 1) / WARPS_PER_BLOCK;
    gap_kernel<<<blocks, THREADS>>>(batch_rep, W_weight, out, num_groups);
}

// round 2
// speedup vs baseline: 1.0030x; 1.0030x over previous
#include <cuda_runtime.h>

// GraphAttentionPooling: B=196608 rows of F=256 fp32, pooled in groups of P=3
// via softmax(x_p . w). Output [G=65536, 256] fp32. Pure streaming, HBM-bound.
//
// R2 changes vs R1 (43.1us, 76.7% DRAM):
//  - hoist all 6 LDG.128 before any reduction (MLP 2 -> 6)
//  - three shfl-reduction chains interleaved (independent, latency overlapped)
//  - __ldcs / __stcs streaming hints (no reuse; keep L2 clean)

constexpr int F = 256;
constexpr int P = 3;
constexpr int WARPS_PER_BLOCK = 8;
constexpr int THREADS = WARPS_PER_BLOCK * 32;

__global__ __launch_bounds__(THREADS)
void gap_kernel(const float* __restrict__ x,
                const float* __restrict__ w,
                float* __restrict__ out,
                int num_groups) {
    __shared__ float ws[F];
    int tid = threadIdx.x;
    ws[tid] = w[tid];
    __syncthreads();

    int warp = tid >> 5;
    int lane = tid & 31;
    int g = blockIdx.x * WARPS_PER_BLOCK + warp;
    if (g >= num_groups) return;

    const float4* wsv = reinterpret_cast<const float4*>(ws) + lane * 2;
    float4 w0 = wsv[0];
    float4 w1 = wsv[1];

    const float4* xg = reinterpret_cast<const float4*>(x) + (size_t)g * (P * F / 4);

    // ---- issue all 6 128-bit loads up front (streaming, evict-first) ----
    float4 r[P][2];
    #pragma unroll
    for (int p = 0; p < P; p++) {
        const float4* row = xg + p * (F / 4);
        r[p][0] = __ldcs(row + lane * 2);
        r[p][1] = __ldcs(row + lane * 2 + 1);
    }

    // ---- per-lane partial dots (independent FMA chains) ----
    float d0 = r[0][0].x * w0.x + r[0][0].y * w0.y + r[0][0].z * w0.z + r[0][0].w * w0.w
             + r[0][1].x * w1.x + r[0][1].y * w1.y + r[0][1].z * w1.z + r[0][1].w * w1.w;
    float d1 = r[1][0].x * w0.x + r[1][0].y * w0.y + r[1][0].z * w0.z + r[1][0].w * w0.w
             + r[1][1].x * w1.x + r[1][1].y * w1.y + r[1][1].z * w1.z + r[1][1].w * w1.w;
    float d2 = r[2][0].x * w0.x + r[2][0].y * w0.y + r[2][0].z * w0.z + r[2][0].w * w0.w
             + r[2][1].x * w1.x + r[2][1].y * w1.y + r[2][1].z * w1.z + r[2][1].w * w1.w;

    // ---- three interleaved butterfly reductions (latency overlapped) ----
    #pragma unroll
    for (int off = 16; off > 0; off >>= 1) {
        d0 += __shfl_xor_sync(0xFFFFFFFFu, d0, off);
        d1 += __shfl_xor_sync(0xFFFFFFFFu, d1, off);
        d2 += __shfl_xor_sync(0xFFFFFFFFu, d2, off);
    }

    // ---- softmax over 3 scalars (bias cancels), all lanes redundant ----
    float m = fmaxf(d0, fmaxf(d1, d2));
    float e0 = __expf(d0 - m);
    float e1 = __expf(d1 - m);
    float e2 = __expf(d2 - m);
    float inv = 1.0f / (e0 + e1 + e2);
    float a0 = e0 * inv, a1 = e1 * inv, a2 = e2 * inv;

    float4 o0, o1;
    o0.x = a0 * r[0][0].x + a1 * r[1][0].x + a2 * r[2][0].x;
    o0.y = a0 * r[0][0].y + a1 * r[1][0].y + a2 * r[2][0].y;
    o0.z = a0 * r[0][0].z + a1 * r[1][0].z + a2 * r[2][0].z;
    o0.w = a0 * r[0][0].w + a1 * r[1][0].w + a2 * r[2][0].w;
    o1.x = a0 * r[0][1].x + a1 * r[1][1].x + a2 * r[2][1].x;
    o1.y = a0 * r[0][1].y + a1 * r[1][1].y + a2 * r[2][1].y;
    o1.z = a0 * r[0][1].z + a1 * r[1][1].z + a2 * r[2][1].z;
    o1.w = a0 * r[0][1].w + a1 * r[1][1].w + a2 * r[2][1].w;

    float4* og = reinterpret_cast<float4*>(out) + (size_t)g * (F / 4);
    __stcs(og + lane * 2, o0);
    __stcs(og + lane * 2 + 1, o1);
}

extern "C" void kernel_launch(void* const* d_in, const int* in_sizes, int n_in,
                              void* d_out, int out_size) {
    const float* batch_rep = (const float*)d_in[0];
    const float* W_weight  = (const float*)d_in[1];
    float* out = (float*)d_out;

    int batch = in_sizes[0] / F;
    int num_groups = batch / P;

    int blocks = (num_groups + WARPS_PER_BLOCK - 1) / WARPS_PER_BLOCK;
    gap_kernel<<<blocks, THREADS>>>(batch_rep, W_weight, out, num_groups);
}